// round 3
// baseline (speedup 1.0000x reference)
#include <cuda_runtime.h>
#include <cuda_bf16.h>
#include <float.h>

// Problem constants
#define B_  8
#define T_  512
#define D_  256
#define S_  64
#define P_  1024
#define R_  12

// Scratch (device globals — no allocation allowed)
__device__ float g_sp[B_ * S_ * D_];        // span-pooled features [B,S,D]
__device__ float g_U [B_ * S_ * R_ * D_];   // U[b,s,r,e] = sum_d sp[b,s,d]*Wb[r,d,e]
__device__ float g_Lh[B_ * S_ * R_];        // head linear term
__device__ float g_Lt[B_ * S_ * R_];        // tail linear term

// ---------------------------------------------------------------------------
// f32x2 packed-math helpers (sm_10x: fma.rn.f32x2 — 2x fp32 FMA throughput;
// ptxas never auto-fuses this from C++, must come via PTX)
// ---------------------------------------------------------------------------
__device__ __forceinline__ unsigned long long ffma2_(unsigned long long a,
                                                     unsigned long long b,
                                                     unsigned long long c) {
    unsigned long long d;
    asm("fma.rn.f32x2 %0, %1, %2, %3;" : "=l"(d) : "l"(a), "l"(b), "l"(c));
    return d;
}
__device__ __forceinline__ unsigned long long pack_dup(float x) {
    unsigned long long d;
    unsigned int xi = __float_as_uint(x);
    asm("mov.b64 %0, {%1, %1};" : "=l"(d) : "r"(xi));
    return d;
}
__device__ __forceinline__ float2 unpack2(unsigned long long v) {
    float2 f;
    asm("mov.b64 {%0, %1}, %2;" : "=f"(f.x), "=f"(f.y) : "l"(v));
    return f;
}

// ---------------------------------------------------------------------------
// Kernel 1: ragged span max-pool + per-span linear projections
// grid = B*S blocks, 256 threads (one thread per feature dim)
// ---------------------------------------------------------------------------
__global__ void pool_linear_kernel(const float* __restrict__ encoded,
                                   const float* __restrict__ W_linear,
                                   const int*   __restrict__ span_starts,
                                   const int*   __restrict__ span_lens)
{
    int bs = blockIdx.x;             // 0..511
    int b  = bs >> 6;
    int s  = bs & (S_ - 1);
    int d  = threadIdx.x;

    int start = span_starts[b * S_ + s];
    int len   = span_lens  [b * S_ + s];
    int end   = start + len + 1;     // reference guarantees end <= T
    if (end > T_) end = T_;

    float m = -FLT_MAX;
    const float* ep = encoded + ((size_t)b * T_ + start) * D_ + d;
    for (int t = start; t < end; ++t) {
        m = fmaxf(m, *ep);
        ep += D_;
    }

    __shared__ float sm[D_];
    sm[d] = m;
    g_sp[(size_t)bs * D_ + d] = m;
    __syncthreads();

    // 24 dot products (12 head-part + 12 tail-part), 8 warps -> 3 each
    int w    = threadIdx.x >> 5;
    int lane = threadIdx.x & 31;
    for (int j = w; j < 24; j += 8) {
        int r    = j % R_;
        int part = j / R_;        // 0 = head half of W_linear, 1 = tail half
        float acc = 0.f;
        #pragma unroll
        for (int i = 0; i < 8; ++i) {
            int dd = i * 32 + lane;
            acc = fmaf(sm[dd], W_linear[(size_t)(part * D_ + dd) * R_ + r], acc);
        }
        #pragma unroll
        for (int o = 16; o; o >>= 1)
            acc += __shfl_xor_sync(0xFFFFFFFFu, acc, o);
        if (lane == 0) {
            if (part) g_Lt[bs * R_ + r] = acc;
            else      g_Lh[bs * R_ + r] = acc;
        }
    }
}

// ---------------------------------------------------------------------------
// Kernel 2: U[b,s,r,e] = sum_d sp[b,s,d] * Wb[r,d,e]
// 12 GEMMs: A = g_sp [512 x 256], B = Wb[r] [256 x 256] -> C_r [512 x 256]
// 128x128 block tile, BK=16, 256 threads, 8x8 register tile, f32x2 FMA.
// Per-thread n-tile split as 4 cols @ tn4 and 4 cols @ tn4+64 so the
// LDS.128 phase addresses are 16B-strided -> conflict-free.
// ---------------------------------------------------------------------------
#define BM 128
#define BN 128
#define BK 16

__global__ __launch_bounds__(256, 1)
void ugemm_kernel(const float* __restrict__ Wb)
{
    const int r  = blockIdx.z;
    const int m0 = blockIdx.y * BM;
    const int n0 = blockIdx.x * BN;

    const float* A  = g_sp;                         // [512, 256] row-major
    const float* Bm = Wb + (size_t)r * D_ * D_;     // [256, 256] row-major

    __shared__ float As[BK][BM + 4];   // transposed: As[k][m], row = 528B (16B-aligned)
    __shared__ float Bs[BK][BN + 4];   // Bs[k][n]

    const int tid = threadIdx.x;       // 0..255

    // global-load mapping
    const int a_row = tid >> 1;            // 0..127
    const int a_k   = (tid & 1) * 8;       // 0 or 8
    const int b_k   = tid >> 4;            // 0..15
    const int b_col = (tid & 15) * 8;      // 0..120

    // compute mapping
    const int tm  = (tid >> 4) * 8;        // 0..120
    const int tn4 = (tid & 15) * 4;        // 0..60  (second group at +64)

    unsigned long long acc[8][4];
    #pragma unroll
    for (int i = 0; i < 8; ++i)
        #pragma unroll
        for (int j = 0; j < 4; ++j)
            acc[i][j] = 0ULL;

    // prefetch slab 0
    float4 pa0 = *(const float4*)&A [(size_t)(m0 + a_row) * D_ + a_k];
    float4 pa1 = *(const float4*)&A [(size_t)(m0 + a_row) * D_ + a_k + 4];
    float4 pb0 = *(const float4*)&Bm[(size_t)b_k * D_ + n0 + b_col];
    float4 pb1 = *(const float4*)&Bm[(size_t)b_k * D_ + n0 + b_col + 4];

    for (int k0 = 0; k0 < D_; k0 += BK) {
        // commit staged slab to smem (A transposed)
        As[a_k + 0][a_row] = pa0.x;
        As[a_k + 1][a_row] = pa0.y;
        As[a_k + 2][a_row] = pa0.z;
        As[a_k + 3][a_row] = pa0.w;
        As[a_k + 4][a_row] = pa1.x;
        As[a_k + 5][a_row] = pa1.y;
        As[a_k + 6][a_row] = pa1.z;
        As[a_k + 7][a_row] = pa1.w;
        *(float4*)&Bs[b_k][b_col]     = pb0;
        *(float4*)&Bs[b_k][b_col + 4] = pb1;
        __syncthreads();

        // prefetch next slab (LDG latency overlaps the ~2K-cycle compute phase)
        if (k0 + BK < D_) {
            pa0 = *(const float4*)&A [(size_t)(m0 + a_row) * D_ + k0 + BK + a_k];
            pa1 = *(const float4*)&A [(size_t)(m0 + a_row) * D_ + k0 + BK + a_k + 4];
            pb0 = *(const float4*)&Bm[(size_t)(k0 + BK + b_k) * D_ + n0 + b_col];
            pb1 = *(const float4*)&Bm[(size_t)(k0 + BK + b_k) * D_ + n0 + b_col + 4];
        }

        #pragma unroll
        for (int k = 0; k < BK; ++k) {
            float4 av0 = *(const float4*)&As[k][tm];        // 2-addr broadcast per warp
            float4 av1 = *(const float4*)&As[k][tm + 4];
            ulonglong2 bq0 = *(const ulonglong2*)&Bs[k][tn4];        // pairs (n,n+1),(n+2,n+3)
            ulonglong2 bq1 = *(const ulonglong2*)&Bs[k][tn4 + 64];
            unsigned long long bb0 = bq0.x, bb1 = bq0.y;
            unsigned long long bb2 = bq1.x, bb3 = bq1.y;
            float aa[8] = {av0.x, av0.y, av0.z, av0.w, av1.x, av1.y, av1.z, av1.w};
            #pragma unroll
            for (int i = 0; i < 8; ++i) {
                unsigned long long ad = pack_dup(aa[i]);
                acc[i][0] = ffma2_(ad, bb0, acc[i][0]);
                acc[i][1] = ffma2_(ad, bb1, acc[i][1]);
                acc[i][2] = ffma2_(ad, bb2, acc[i][2]);
                acc[i][3] = ffma2_(ad, bb3, acc[i][3]);
            }
        }
        __syncthreads();
    }

    // store: columns n0+tn4+{0..3} and n0+64+tn4+{0..3} for rows m0+tm+i
    #pragma unroll
    for (int i = 0; i < 8; ++i) {
        float2 c01 = unpack2(acc[i][0]);
        float2 c23 = unpack2(acc[i][1]);
        float2 c45 = unpack2(acc[i][2]);
        float2 c67 = unpack2(acc[i][3]);
        size_t base = ((size_t)(m0 + tm + i) * R_ + r) * D_;
        *(float4*)&g_U[base + n0 + tn4]      = make_float4(c01.x, c01.y, c23.x, c23.y);
        *(float4*)&g_U[base + n0 + 64 + tn4] = make_float4(c45.x, c45.y, c67.x, c67.y);
    }
}

// ---------------------------------------------------------------------------
// Kernel 3: per-pair score. One warp per pair.
// score[r] = Lh[head,r] + Lt[tail,r] + bias[r] + dot(U[head,r,:], sp[tail,:])
// out = sigmoid(score)
// ---------------------------------------------------------------------------
__global__ void pair_kernel(const int*   __restrict__ pair_head,
                            const int*   __restrict__ pair_tail,
                            const float* __restrict__ b_linear,
                            float*       __restrict__ out)
{
    int g    = blockIdx.x * 8 + (threadIdx.x >> 5);   // global pair id 0..8191
    int lane = threadIdx.x & 31;
    int b    = g >> 10;
    int p    = g & (P_ - 1);

    int h = pair_head[b * P_ + p];
    int t = pair_tail[b * P_ + p];

    const float* tvp = g_sp + (size_t)(b * S_ + t) * D_;
    float tv[8];
    #pragma unroll
    for (int i = 0; i < 8; ++i) tv[i] = tvp[i * 32 + lane];

    const float* Up  = g_U  + (size_t)(b * S_ + h) * R_ * D_;
    const float* Lhp = g_Lh + (b * S_ + h) * R_;
    const float* Ltp = g_Lt + (b * S_ + t) * R_;

    #pragma unroll
    for (int r = 0; r < R_; ++r) {
        float acc = 0.f;
        const float* ur = Up + r * D_;
        #pragma unroll
        for (int i = 0; i < 8; ++i)
            acc = fmaf(ur[i * 32 + lane], tv[i], acc);
        #pragma unroll
        for (int o = 16; o; o >>= 1)
            acc += __shfl_xor_sync(0xFFFFFFFFu, acc, o);
        if (lane == 0) {
            float x = acc + Lhp[r] + Ltp[r] + b_linear[r];
            out[(size_t)(b * P_ + p) * R_ + r] = 1.f / (1.f + __expf(-x));
        }
    }
}

// ---------------------------------------------------------------------------
extern "C" void kernel_launch(void* const* d_in, const int* in_sizes, int n_in,
                              void* d_out, int out_size)
{
    const float* encoded     = (const float*)d_in[0];  // [8,512,256]
    const float* W_linear    = (const float*)d_in[1];  // [512,12]
    const float* b_linear    = (const float*)d_in[2];  // [12]
    const float* W_bilinear  = (const float*)d_in[3];  // [12,256,256]
    const int*   span_starts = (const int*)  d_in[4];  // [8,64]
    const int*   span_lens   = (const int*)  d_in[5];  // [8,64]
    const int*   pair_head   = (const int*)  d_in[6];  // [8,1024]
    const int*   pair_tail   = (const int*)  d_in[7];  // [8,1024]
    float*       out         = (float*)d_out;          // [8,1024,12]

    pool_linear_kernel<<<B_ * S_, 256>>>(encoded, W_linear, span_starts, span_lens);

    dim3 ggrid(D_ / BN, (B_ * S_) / BM, R_);  // (2, 4, 12) = 96 blocks
    ugemm_kernel<<<ggrid, 256>>>(W_bilinear);

    pair_kernel<<<(B_ * P_) / 8, 256>>>(pair_head, pair_tail, b_linear, out);
}